// round 2
// baseline (speedup 1.0000x reference)
#include <cuda_runtime.h>
#include <math.h>

#define B_ 2
#define T_ 32
#define H_ 64
#define W_ 64
#define C_ 32
#define WR_ 33
#define KS_ 15

// Intermediates (allocation-free: __device__ globals)
__device__ float2 d_R [B_*C_*WR_*T_*H_];   // (B,C,Wr,T,H) row-FFT output
__device__ float2 d_Yr[B_*C_*WR_*T_*H_];   // (B,C,Wr,T,H) after col-inv FFT
__device__ float2 d_Kf[2*C_*WR_*H_];       // (2,C,Wr,H) kernel spectra
__device__ float  d_ctx[B_*T_*C_];
__device__ float  d_gates[B_*C_*4*T_];     // (B,C,[a,d,m,g],T)

__device__ __forceinline__ float2 cmul(float2 a, float2 b){
  return make_float2(a.x*b.x - a.y*b.y, a.x*b.y + a.y*b.x);
}

__device__ __forceinline__ void init_tw(float2* tw, int tid){
  if (tid < 32){
    float s, c;
    sincosf(-6.283185307179586f * (float)tid / 64.0f, &s, &c);
    tw[tid] = make_float2(c, s);
  }
}

// Batched in-place 64-point complex FFT over NB contiguous rows in smem.
// Bit-reversal permutation + 6 radix-2 DIT stages. INV=1: conj twiddles, UNSCALED.
template<int INV>
__device__ void fft64_batch(float2* d, int NB, const float2* tw, int tid, int nt){
  for (int i = tid; i < NB*64; i += nt){
    int row = i >> 6, pos = i & 63;
    int r = (int)(__brev((unsigned)pos) >> 26);
    if (pos < r){
      float2 a = d[(row<<6)+pos];
      d[(row<<6)+pos] = d[(row<<6)+r];
      d[(row<<6)+r] = a;
    }
  }
  __syncthreads();
  #pragma unroll
  for (int s = 1; s <= 6; s++){
    int half = 1 << (s-1);
    for (int j = tid; j < NB*32; j += nt){
      int row = j >> 5, jj = j & 31;
      int grp = jj >> (s-1), pos = jj & (half-1);
      int i0 = (row<<6) + grp*(half<<1) + pos;
      int i1 = i0 + half;
      float2 w = tw[pos << (6-s)];
      if (INV) w.y = -w.y;
      float2 u = d[i0];
      float2 v = cmul(w, d[i1]);
      d[i0] = make_float2(u.x+v.x, u.y+v.y);
      d[i1] = make_float2(u.x-v.x, u.y-v.y);
    }
    __syncthreads();
  }
}

// ---------------- K1: row rfft of x (4 channels per block) + ctx means ----------------
// block = (b, t, cg); cg indexes a float4-aligned group of 4 channels (8 groups).
__global__ void k_fwd(const float* __restrict__ x){
  __shared__ float2 pb[32*64];   // 16 h rows per chunk, 2 packed complex rows each
  __shared__ float2 tw[32];
  __shared__ float rs[8][4];
  int tid = threadIdx.x;
  int bid = blockIdx.x;
  int cg = bid & 7, t = (bid>>3) & 31, b = bid >> 8;
  init_tw(tw, tid);
  const float4* xb = (const float4*)x + (size_t)(b*T_ + t)*H_*W_*8 + cg;
  float a0=0.f,a1=0.f,a2=0.f,a3=0.f;

  for (int hc = 0; hc < 64; hc += 16){
    __syncthreads();
    for (int i = tid; i < 16*64; i += 256){
      int hl = i >> 6, w = i & 63;
      float4 v = xb[(size_t)((hc+hl)*64 + w)*8];
      pb[((hl<<1)+0)*64 + w] = make_float2(v.x, v.y);  // pack (c0 + i c1)
      pb[((hl<<1)+1)*64 + w] = make_float2(v.z, v.w);  // pack (c2 + i c3)
      a0 += v.x; a1 += v.y; a2 += v.z; a3 += v.w;
    }
    __syncthreads();
    fft64_batch<0>(pb, 32, tw, tid, 256);
    // unpack real-pair spectra, keep wr = 0..32, write to d_R (B,C,Wr,T,H)
    // mapping: pr fastest so a warp covers all 32 packed rows at one wr
    // -> per (c,wr) a warp writes 16 contiguous h (128B runs)
    for (int i = tid; i < 32*33; i += 256){
      int pr = i & 31, k = i >> 5;
      int hl = pr >> 1, p = pr & 1;
      int h = hc + hl;
      float2 Z  = pb[(pr<<6) + k];
      float2 Zc = pb[(pr<<6) + ((64-k)&63)];
      float2 A  = make_float2(0.5f*(Z.x+Zc.x),  0.5f*(Z.y-Zc.y));   // FFT(even ch)
      float2 Bv = make_float2(0.5f*(Z.y+Zc.y), -0.5f*(Z.x-Zc.x));   // FFT(odd ch)
      int c0 = (cg<<2) + (p<<1);
      d_R[ ((((size_t)(b*C_ + c0    )*WR_ + k)*T_ + t)<<6) + h ] = A;
      d_R[ ((((size_t)(b*C_ + c0 + 1)*WR_ + k)*T_ + t)<<6) + h ] = Bv;
    }
  }
  // ctx reduction
  #pragma unroll
  for (int off=16; off; off>>=1){
    a0 += __shfl_down_sync(0xffffffffu, a0, off);
    a1 += __shfl_down_sync(0xffffffffu, a1, off);
    a2 += __shfl_down_sync(0xffffffffu, a2, off);
    a3 += __shfl_down_sync(0xffffffffu, a3, off);
  }
  int lane = tid & 31, warp = tid >> 5;
  if (lane == 0){ rs[warp][0]=a0; rs[warp][1]=a1; rs[warp][2]=a2; rs[warp][3]=a3; }
  __syncthreads();
  if (tid < 4){
    float s = 0.f;
    #pragma unroll
    for (int w = 0; w < 8; w++) s += rs[w][tid];
    d_ctx[(b*T_ + t)*C_ + (cg<<2) + tid] = s * (1.0f/4096.0f);
  }
}

// ---------------- K2: gates (tiny GEMMs + activations) ----------------
__global__ void k_gates(const float* __restrict__ wA, const float* __restrict__ bA,
                        const float* __restrict__ wD, const float* __restrict__ bD,
                        const float* __restrict__ wM, const float* __restrict__ bM,
                        const float* __restrict__ wG, const float* __restrict__ bG,
                        const float* __restrict__ decay){
  __shared__ float sctx[32];
  int bt = blockIdx.x;        // b*T + t
  int c = threadIdx.x;
  sctx[c] = d_ctx[bt*32 + c];
  __syncwarp();
  float za = bA[c], zd = bD[c], zm = bM[c], zg = bG[c];
  #pragma unroll
  for (int k = 0; k < 32; k++){
    float v = sctx[k];
    za += v * wA[k*32 + c];
    zd += v * wD[k*32 + c];
    zm += v * wM[k*32 + c];
    zg += v * wG[k*32 + c];
  }
  float dec = fminf(fmaxf(decay[c], 0.1f), 0.99f);
  float ga = dec / (1.0f + expf(-za));
  float gd = dec / (1.0f + expf(-zd));
  float gm = (zm > 20.0f) ? zm : log1pf(expf(zm));
  float gg = (zg > 20.0f) ? zg : log1pf(expf(zg));
  int b = bt >> 5, t = bt & 31;
  int base = ((b*32 + c)*4)*32 + t;
  d_gates[base +  0] = ga;
  d_gates[base + 32] = gd;
  d_gates[base + 64] = gm;
  d_gates[base + 96] = gg;
}

// ---------------- K3: padded rfft2 of conv kernels ----------------
__global__ void k_kf(const float* __restrict__ ke, const float* __restrict__ ki){
  __shared__ float2 pb[32*64];
  __shared__ float2 buf2[33*64];   // [wr][h]
  __shared__ float2 tw[32];
  int tid = threadIdx.x;
  int e = blockIdx.x >> 5, c = blockIdx.x & 31;
  const float* kk = (e ? ki : ke) + c*KS_*KS_;
  init_tw(tw, tid);
  // padded plane (offset 24) packed as (row 2pr) + i*(row 2pr+1)
  for (int i = tid; i < 32*64; i += 256){
    int pr = i >> 6, w = i & 63;
    int h0 = pr << 1;
    float v0 = 0.f, v1 = 0.f;
    if (w >= 24 && w < 39){
      if (h0   >= 24 && h0   < 39) v0 = kk[(h0  -24)*15 + (w-24)];
      if (h0+1 >= 24 && h0+1 < 39) v1 = kk[(h0+1-24)*15 + (w-24)];
    }
    pb[i] = make_float2(v0, v1);
  }
  __syncthreads();
  fft64_batch<0>(pb, 32, tw, tid, 256);
  for (int i = tid; i < 32*33; i += 256){
    int pr = i / 33, k = i - pr*33;
    float2 Z  = pb[(pr<<6)+k];
    float2 Zc = pb[(pr<<6) + ((64-k)&63)];
    float2 A  = make_float2(0.5f*(Z.x+Zc.x),  0.5f*(Z.y-Zc.y));
    float2 Bv = make_float2(0.5f*(Z.y+Zc.y), -0.5f*(Z.x-Zc.x));
    buf2[(k<<6) + (pr<<1)    ] = A;    // transposed: [wr][h]
    buf2[(k<<6) + (pr<<1) + 1] = Bv;
  }
  __syncthreads();
  fft64_batch<0>(buf2, 33, tw, tid, 256);   // column FFT over h
  for (int i = tid; i < 33*64; i += 256)
    d_Kf[(e*32 + c)*2112 + i] = buf2[i];
}

// ---------------- K4: col FFT + linear recurrence over T + inverse col FFT ----------------
// block = (b,c,wr): full (t,h) tile in 16KB smem; U_hat/Y_hat never hit DRAM.
__global__ void k_mid(){
  __shared__ float2 tile[32*64];   // [t][h]
  __shared__ float2 sKE[64], sKI[64];
  __shared__ float2 tw[32];
  __shared__ float  sg[128];       // [a(32) d(32) m(32) g(32)]
  int tid = threadIdx.x;
  int bid = blockIdx.x;            // (b*C + c)*33 + wr
  int bc  = bid / 33;
  int wr  = bid - bc*33;
  int c   = bc & 31;
  init_tw(tw, tid);
  size_t rbase = (size_t)bid * 2048;
  for (int i = tid; i < 2048; i += 256) tile[i] = d_R[rbase + i];
  if (tid < 64){
    sKE[tid] = d_Kf[(size_t)c*2112        + wr*64 + tid];
    sKI[tid] = d_Kf[(size_t)(32+c)*2112   + wr*64 + tid];
  }
  if (tid < 128) sg[tid] = d_gates[bc*128 + tid];
  __syncthreads();
  fft64_batch<0>(tile, 32, tw, tid, 256);     // forward FFT along h per t
  if (tid < 64){
    int h = tid;
    float2 KE = sKE[h], KI = sKI[h];
    float2 X = make_float2(0.f,0.f), Y = make_float2(0.f,0.f);
    #pragma unroll
    for (int t = 0; t < 32; t++){
      float a = sg[t], dd = sg[32+t], m = sg[64+t], g = sg[96+t];
      float2 U   = tile[(t<<6) + h];
      float2 KIY = cmul(KI, Y);
      float2 KEX = cmul(KE, X);
      float2 nX = make_float2(a*X.x - m*KIY.x + U.x, a*X.y - m*KIY.y + U.y);
      float2 nY = make_float2(g*KEX.x + dd*Y.x + 1e-10f, g*KEX.y + dd*Y.y);
      tile[(t<<6) + h] = nY;
      X = nX; Y = nY;
    }
  }
  __syncthreads();
  fft64_batch<1>(tile, 32, tw, tid, 256);     // inverse FFT along h (unscaled)
  for (int i = tid; i < 2048; i += 256) d_Yr[rbase + i] = tile[i];
}

// ---------------- K5: inverse row rfft + scale + scatter to (B,T,H,W,C) ----------------
__global__ void k_inv(float* __restrict__ out){
  __shared__ float2 ft[64*33];     // [h][wr]
  __shared__ float2 wb[32*64];     // packed rows
  __shared__ float2 tw[32];
  int tid = threadIdx.x;
  int bid = blockIdx.x;            // (b*T + t)*C + c  (c fastest -> L2 write merge)
  int c = bid & 31;
  int t = (bid >> 5) & 31;
  int b = bid >> 10;
  init_tw(tw, tid);
  size_t ybase = ((size_t)(b*32 + c)*33)*2048 + ((size_t)t<<6);
  for (int i = tid; i < 33*64; i += 256){
    int wr = i >> 6, h = i & 63;
    ft[h*33 + wr] = d_Yr[ybase + (size_t)wr*2048 + h];
  }
  __syncthreads();
  // Hermitian extend + pack pairs of h rows: z = A0 + i*A1
  for (int i = tid; i < 32*64; i += 256){
    int pr = i >> 6, k = i & 63;
    int r0 = pr << 1, r1 = r0 + 1;
    float2 A0, A1;
    if (k <= 32){ A0 = ft[r0*33 + k]; A1 = ft[r1*33 + k]; }
    else {
      A0 = ft[r0*33 + (64 - k)]; A0.y = -A0.y;
      A1 = ft[r1*33 + (64 - k)]; A1.y = -A1.y;
    }
    wb[i] = make_float2(A0.x - A1.y, A0.y + A1.x);
  }
  __syncthreads();
  fft64_batch<1>(wb, 32, tw, tid, 256);       // unscaled inverse
  const float sc = 1.0f/4096.0f;              // full irfft2 normalization
  size_t obase = ((size_t)(b*32 + t)*4096)*32 + c;
  for (int i = tid; i < 32*64; i += 256){
    int pr = i >> 6, n = i & 63;
    float2 v = wb[i];
    out[obase + (size_t)(((pr<<1)  )*64 + n)*32] = v.x * sc;
    out[obase + (size_t)(((pr<<1)+1)*64 + n)*32] = v.y * sc;
  }
}

extern "C" void kernel_launch(void* const* d_in, const int* in_sizes, int n_in,
                              void* d_out, int out_size){
  const float* x  = (const float*)d_in[0];
  const float* wA = (const float*)d_in[1];
  const float* bA = (const float*)d_in[2];
  const float* wD = (const float*)d_in[3];
  const float* bD = (const float*)d_in[4];
  const float* wM = (const float*)d_in[5];
  const float* bM = (const float*)d_in[6];
  const float* wG = (const float*)d_in[7];
  const float* bG = (const float*)d_in[8];
  const float* dc = (const float*)d_in[9];
  const float* ke = (const float*)d_in[10];
  const float* ki = (const float*)d_in[11];
  float* out = (float*)d_out;

  k_fwd  <<<B_*T_*8,   256>>>(x);                    // 512 blocks (b,t,cg)
  k_gates<<<B_*T_,     32>>>(wA,bA,wD,bD,wM,bM,wG,bG,dc);
  k_kf   <<<2*C_,      256>>>(ke, ki);
  k_mid  <<<B_*C_*WR_, 256>>>();                     // 2112 blocks
  k_inv  <<<B_*T_*C_,  256>>>(out);                  // 2048 blocks
}

// round 3
// speedup vs baseline: 1.0441x; 1.0441x over previous
#include <cuda_runtime.h>
#include <math.h>

#define B_ 2
#define T_ 32
#define H_ 64
#define W_ 64
#define C_ 32
#define WR_ 33
#define KS_ 15

// Intermediates (allocation-free: __device__ globals)
__device__ float2 d_R [B_*C_*WR_*T_*H_];   // (B,C,Wr,T,H) row-FFT output (h spatial)
__device__ float2 d_Yr[B_*C_*WR_*T_*H_];   // (B,C,Wr,T,H) after col-inv FFT
__device__ float2 d_Kf[2*C_*WR_*H_];       // (2,C,Wr,slot) kernel spectra, slot-permuted
__device__ float  d_ctx[B_*T_*C_];
__device__ float  d_gates[B_*C_*4*T_];     // (B,C,[a,d,m,g],T)

__device__ __forceinline__ float2 cmul(float2 a, float2 b){
  return make_float2(a.x*b.x - a.y*b.y, a.x*b.y + a.y*b.x);
}

// ---------------- register FFT8, DIF + output reorder to natural order ----------------
template<int INV>
__device__ __forceinline__ void fft8r(float2 v[8]){
  const float S = 0.70710678118654752f;
  // stage 1 (span 4), twiddles W8^i on lower output
  {
    float2 u, w, d;
    u=v[0]; w=v[4]; v[0]=make_float2(u.x+w.x,u.y+w.y); v[4]=make_float2(u.x-w.x,u.y-w.y);
    u=v[1]; w=v[5]; v[1]=make_float2(u.x+w.x,u.y+w.y); d=make_float2(u.x-w.x,u.y-w.y);
    v[5]= INV? make_float2(S*(d.x-d.y), S*(d.x+d.y)) : make_float2(S*(d.x+d.y), S*(d.y-d.x));
    u=v[2]; w=v[6]; v[2]=make_float2(u.x+w.x,u.y+w.y); d=make_float2(u.x-w.x,u.y-w.y);
    v[6]= INV? make_float2(-d.y, d.x) : make_float2(d.y, -d.x);
    u=v[3]; w=v[7]; v[3]=make_float2(u.x+w.x,u.y+w.y); d=make_float2(u.x-w.x,u.y-w.y);
    v[7]= INV? make_float2(-S*(d.x+d.y), S*(d.x-d.y)) : make_float2(S*(d.y-d.x), -S*(d.x+d.y));
  }
  // stage 2 (span 2), twiddles 1, -i (fwd) per half
  #pragma unroll
  for (int h=0; h<8; h+=4){
    float2 u, w, d;
    u=v[h];   w=v[h+2]; v[h]  =make_float2(u.x+w.x,u.y+w.y); v[h+2]=make_float2(u.x-w.x,u.y-w.y);
    u=v[h+1]; w=v[h+3]; v[h+1]=make_float2(u.x+w.x,u.y+w.y); d=make_float2(u.x-w.x,u.y-w.y);
    v[h+3]= INV? make_float2(-d.y, d.x) : make_float2(d.y, -d.x);
  }
  // stage 3 (span 1)
  #pragma unroll
  for (int h=0; h<8; h+=2){
    float2 u=v[h], w=v[h+1];
    v[h]  =make_float2(u.x+w.x,u.y+w.y);
    v[h+1]=make_float2(u.x-w.x,u.y-w.y);
  }
  // bit-reverse outputs -> natural order
  float2 t1=v[1]; v[1]=v[4]; v[4]=t1;
  float2 t3=v[3]; v[3]=v[6]; v[6]=t3;
}

// ---------------- register FFT64 over 8 lanes x 8 regs ----------------
// Forward: input  (lane j = n2, reg n1): x[8*n1 + j]
//          output (lane k1, reg k2):     X[k1 + 8*k2]
// Inverse (conj, unscaled): exact inverse mapping of the above.
// tw[r] = exp(-2*pi*i * lane * r / 64)
template<int INV>
__device__ __forceinline__ void fft64r(float2 v[8], const float2 tw[8], int lane8){
  fft8r<INV>(v);
  #pragma unroll
  for (int r=1;r<8;r++){
    float2 w = tw[r];
    if (INV) w.y = -w.y;
    v[r] = cmul(v[r], w);
  }
  // 8x8 transpose across lanes (reg index <-> lane index)
  #pragma unroll
  for (int m=4; m; m>>=1){
    #pragma unroll
    for (int i=0;i<8;i++){
      if (i & m) continue;
      bool up = (lane8 & m) != 0;
      float2 send = up ? v[i] : v[i+m];
      float2 got;
      got.x = __shfl_xor_sync(0xffffffffu, send.x, m);
      got.y = __shfl_xor_sync(0xffffffffu, send.y, m);
      if (up) v[i] = got; else v[i+m] = got;
    }
  }
  fft8r<INV>(v);
}

__device__ __forceinline__ void make_tw(float2 tw[8], int j){
  tw[0] = make_float2(1.f, 0.f);
  #pragma unroll
  for (int r=1;r<8;r++){
    float s, c;
    __sincosf(-0.098174770424681f * (float)(j*r), &s, &c);
    tw[r] = make_float2(c, s);
  }
}

// Hermitian partner fetch: rc[r] = Z[(64 - (j+8r)) mod 64], within 8-lane groups.
__device__ __forceinline__ void herm_partner(const float2 v[8], float2 rc[8], int j){
  int src = (8 - j) & 7;
  #pragma unroll
  for (int r=0;r<8;r++){
    float2 send = v[7-r];
    float2 got;
    got.x = __shfl_sync(0xffffffffu, send.x, src, 8);
    got.y = __shfl_sync(0xffffffffu, send.y, src, 8);
    rc[r] = got;
  }
  if (j == 0){
    rc[0]=v[0]; rc[1]=v[7]; rc[2]=v[6]; rc[3]=v[5];
    rc[4]=v[4]; rc[5]=v[3]; rc[6]=v[2]; rc[7]=v[1];
  }
}

// ---------------- K1: row rfft of x (reg FFT, no data smem) + ctx means ----------------
// block = (b, t, cg), cg in 0..7 (4 channels each -> 2 packed complex rows per h)
__global__ void k_fwd(const float* __restrict__ x){
  __shared__ float wsum[8][4];
  int tid = threadIdx.x, bid = blockIdx.x;
  int cg = bid & 7, t = (bid>>3) & 31, b = bid >> 8;
  int j = tid & 7, g = tid >> 3;          // 32 groups of 8 lanes
  float2 tw[8]; make_tw(tw, j);
  const float* xb = x + (size_t)(b*T_ + t)*H_*W_*C_;
  float a0 = 0.f, a1 = 0.f;
  int p = g & 1;                          // pack parity (constant across iters)
  int cbase = cg*4 + p*2;

  for (int it=0; it<4; it++){
    int R = it*32 + g;
    int h = R >> 1;
    const float* row = xb + (size_t)h*W_*C_ + cbase;
    float2 v[8];
    #pragma unroll
    for (int n1=0;n1<8;n1++){
      float2 z = *(const float2*)(row + (size_t)(8*n1 + j)*C_);
      v[n1] = z; a0 += z.x; a1 += z.y;
    }
    fft64r<0>(v, tw, j);                  // lane=k1, reg=k2, k = j + 8*k2
    float2 rc[8];
    herm_partner(v, rc, j);
    #pragma unroll
    for (int r=0;r<8;r++){
      int k = j + 8*r;
      if (k <= 32){
        float2 A  = make_float2(0.5f*(v[r].x + rc[r].x), 0.5f*(v[r].y - rc[r].y));
        float2 Bv = make_float2(0.5f*(v[r].y + rc[r].y), 0.5f*(rc[r].x - v[r].x));
        size_t o0 = ((size_t)(b*C_ + cbase    )*WR_ + k)*2048 + (size_t)t*64 + h;
        size_t o1 = ((size_t)(b*C_ + cbase + 1)*WR_ + k)*2048 + (size_t)t*64 + h;
        d_R[o0] = A;
        d_R[o1] = Bv;
      }
    }
  }
  // ctx: combine lanes of same p (lane^16 same p), then over j bits
  a0 += __shfl_xor_sync(0xffffffffu, a0, 16);
  a1 += __shfl_xor_sync(0xffffffffu, a1, 16);
  #pragma unroll
  for (int m=4;m;m>>=1){
    a0 += __shfl_xor_sync(0xffffffffu, a0, m);
    a1 += __shfl_xor_sync(0xffffffffu, a1, m);
  }
  int lane = tid & 31, warp = tid >> 5;
  if (lane == 0){ wsum[warp][0]=a0; wsum[warp][1]=a1; }
  if (lane == 8){ wsum[warp][2]=a0; wsum[warp][3]=a1; }
  __syncthreads();
  if (tid < 4){
    float s = 0.f;
    #pragma unroll
    for (int w=0;w<8;w++) s += wsum[w][tid];
    d_ctx[(b*T_ + t)*C_ + cg*4 + tid] = s * (1.0f/4096.0f);
  }
}

// ---------------- K2: gates ----------------
__global__ void k_gates(const float* __restrict__ wA, const float* __restrict__ bA,
                        const float* __restrict__ wD, const float* __restrict__ bD,
                        const float* __restrict__ wM, const float* __restrict__ bM,
                        const float* __restrict__ wG, const float* __restrict__ bG,
                        const float* __restrict__ decay){
  __shared__ float sctx[32];
  int bt = blockIdx.x;
  int c = threadIdx.x;
  sctx[c] = d_ctx[bt*32 + c];
  __syncwarp();
  float za = bA[c], zd = bD[c], zm = bM[c], zg = bG[c];
  #pragma unroll
  for (int k = 0; k < 32; k++){
    float v = sctx[k];
    za += v * wA[k*32 + c];
    zd += v * wD[k*32 + c];
    zm += v * wM[k*32 + c];
    zg += v * wG[k*32 + c];
  }
  float dec = fminf(fmaxf(decay[c], 0.1f), 0.99f);
  float ga = dec / (1.0f + expf(-za));
  float gd = dec / (1.0f + expf(-zd));
  float gm = (zm > 20.0f) ? zm : log1pf(expf(zm));
  float gg = (zg > 20.0f) ? zg : log1pf(expf(zg));
  int b = bt >> 5, t = bt & 31;
  int base = (b*32 + c)*128 + t;
  d_gates[base +  0] = ga;
  d_gates[base + 32] = gd;
  d_gates[base + 64] = gm;
  d_gates[base + 96] = gg;
}

// ---------------- K3: padded rfft2 of conv kernels, slot-permuted column spectra ----------------
__global__ void k_kf(const float* __restrict__ ke, const float* __restrict__ ki){
  __shared__ float2 sb[WR_*64];       // [wr][h spatial]
  int tid = threadIdx.x;
  int e = blockIdx.x >> 5, c = blockIdx.x & 31;
  const float* kk = (e ? ki : ke) + c*KS_*KS_;
  int j = tid & 7, g = tid >> 3;
  float2 tw[8]; make_tw(tw, j);

  // row FFT over w for packed h pairs (g = pr -> rows 2g, 2g+1), padded plane offset 24
  {
    int h0 = g << 1;
    float2 v[8];
    #pragma unroll
    for (int n1=0;n1<8;n1++){
      int w = 8*n1 + j;
      float v0 = 0.f, v1 = 0.f;
      if (w >= 24 && w < 39){
        if (h0   >= 24 && h0   < 39) v0 = kk[(h0  -24)*KS_ + (w-24)];
        if (h0+1 >= 24 && h0+1 < 39) v1 = kk[(h0+1-24)*KS_ + (w-24)];
      }
      v[n1] = make_float2(v0, v1);
    }
    fft64r<0>(v, tw, j);
    float2 rc[8];
    herm_partner(v, rc, j);
    #pragma unroll
    for (int r=0;r<8;r++){
      int k = j + 8*r;
      if (k <= 32){
        float2 A  = make_float2(0.5f*(v[r].x + rc[r].x), 0.5f*(v[r].y - rc[r].y));
        float2 Bv = make_float2(0.5f*(v[r].y + rc[r].y), 0.5f*(rc[r].x - v[r].x));
        sb[k*64 + h0    ] = A;
        sb[k*64 + h0 + 1] = Bv;
      }
    }
  }
  __syncthreads();
  // column FFT over h, rows wr=0..31 by groups; output slot = k2*8 + k1 (matches k_mid)
  size_t kb = ((size_t)(e*C_ + c)*WR_)*64;
  {
    int wr = g;
    float2 v[8];
    #pragma unroll
    for (int n1=0;n1<8;n1++) v[n1] = sb[wr*64 + 8*n1 + j];
    fft64r<0>(v, tw, j);
    #pragma unroll
    for (int r=0;r<8;r++) d_Kf[kb + (size_t)wr*64 + r*8 + j] = v[r];
  }
  // tail row wr=32: whole warp 0 (4 duplicate groups), store from group 0 only
  if (tid < 32){
    float2 v[8];
    #pragma unroll
    for (int n1=0;n1<8;n1++) v[n1] = sb[32*64 + 8*n1 + j];
    fft64r<0>(v, tw, j);
    if ((tid >> 3) == 0){
      #pragma unroll
      for (int r=0;r<8;r++) d_Kf[kb + (size_t)32*64 + r*8 + j] = v[r];
    }
  }
}

// ---------------- K4: col reg-FFT + recurrence over T + inverse col reg-FFT ----------------
// block = (b,c,wr). Frequency order stays slot-permuted (slot = k2*8 + k1).
__global__ void k_mid(){
  __shared__ float sur[32*72];
  __shared__ float sui[32*72];
  __shared__ float sg[128];
  int tid = threadIdx.x;
  int bid = blockIdx.x;
  int bc  = bid / 33;
  int wr  = bid - bc*33;
  int c   = bc & 31;
  int j = tid & 7, t = tid >> 3;
  float2 tw[8]; make_tw(tw, j);
  size_t rbase = (size_t)bid * 2048;

  if (tid < 128) sg[tid] = d_gates[bc*128 + tid];

  float2 v[8];
  #pragma unroll
  for (int n1=0;n1<8;n1++) v[n1] = d_R[rbase + t*64 + 8*n1 + j];
  fft64r<0>(v, tw, j);                  // lane=k1, reg=k2
  #pragma unroll
  for (int r=0;r<8;r++){
    sur[t*72 + r*8 + j] = v[r].x;
    sui[t*72 + r*8 + j] = v[r].y;
  }
  __syncthreads();

  if (tid < 64){
    int slot = tid;
    float2 KE = d_Kf[((size_t)(      c)*WR_ + wr)*64 + slot];
    float2 KI = d_Kf[((size_t)(C_ +  c)*WR_ + wr)*64 + slot];
    float2 X = make_float2(0.f,0.f), Y = make_float2(0.f,0.f);
    #pragma unroll
    for (int t2=0; t2<32; t2++){
      float a  = sg[t2], dd = sg[32+t2], m = sg[64+t2], gg = sg[96+t2];
      float2 U = make_float2(sur[t2*72 + slot], sui[t2*72 + slot]);
      float2 KIY = cmul(KI, Y);
      float2 KEX = cmul(KE, X);
      float2 nX = make_float2(a*X.x - m*KIY.x + U.x, a*X.y - m*KIY.y + U.y);
      float2 nY = make_float2(gg*KEX.x + dd*Y.x + 1e-10f, gg*KEX.y + dd*Y.y);
      sur[t2*72 + slot] = nY.x;
      sui[t2*72 + slot] = nY.y;
      X = nX; Y = nY;
    }
  }
  __syncthreads();

  #pragma unroll
  for (int r=0;r<8;r++){
    v[r].x = sur[t*72 + r*8 + j];
    v[r].y = sui[t*72 + r*8 + j];
  }
  fft64r<1>(v, tw, j);                  // back to spatial h (unscaled)
  #pragma unroll
  for (int n1=0;n1<8;n1++) d_Yr[rbase + t*64 + 8*n1 + j] = v[n1];
}

// ---------------- K5: inverse row rfft + scale + scatter to (B,T,H,W,C) ----------------
__global__ void k_inv(float* __restrict__ out){
  __shared__ float syr[64*WR_];
  __shared__ float syi[64*WR_];
  int tid = threadIdx.x;
  int bid = blockIdx.x;
  int c = bid & 31;
  int t = (bid >> 5) & 31;
  int b = bid >> 10;
  int j = tid & 7, pr = tid >> 3;
  float2 tw[8]; make_tw(tw, j);

  size_t ybase = ((size_t)(b*C_ + c)*WR_)*2048 + (size_t)t*64;
  for (int i = tid; i < WR_*64; i += 256){
    int wr = i >> 6, h = i & 63;
    float2 z = d_Yr[ybase + (size_t)wr*2048 + h];
    syr[h*WR_ + wr] = z.x;
    syi[h*WR_ + wr] = z.y;
  }
  __syncthreads();

  float2 v[8];
  #pragma unroll
  for (int r=0;r<8;r++){
    int k = j + 8*r;
    int wrk = (k <= 32) ? k : 64 - k;
    float sgn = (k <= 32) ? 1.f : -1.f;
    float y0r = syr[(2*pr  )*WR_ + wrk];
    float y0i = sgn * syi[(2*pr  )*WR_ + wrk];
    float y1r = syr[(2*pr+1)*WR_ + wrk];
    float y1i = sgn * syi[(2*pr+1)*WR_ + wrk];
    v[r] = make_float2(y0r - y1i, y0i + y1r);
  }
  fft64r<1>(v, tw, j);
  const float sc = 1.0f/4096.0f;
  size_t obase = ((size_t)(b*T_ + t)*4096)*32 + c;
  #pragma unroll
  for (int n1=0;n1<8;n1++){
    int w = 8*n1 + j;
    out[obase + (size_t)((2*pr  )*64 + w)*32] = v[n1].x * sc;
    out[obase + (size_t)((2*pr+1)*64 + w)*32] = v[n1].y * sc;
  }
}

extern "C" void kernel_launch(void* const* d_in, const int* in_sizes, int n_in,
                              void* d_out, int out_size){
  const float* x  = (const float*)d_in[0];
  const float* wA = (const float*)d_in[1];
  const float* bA = (const float*)d_in[2];
  const float* wD = (const float*)d_in[3];
  const float* bD = (const float*)d_in[4];
  const float* wM = (const float*)d_in[5];
  const float* bM = (const float*)d_in[6];
  const float* wG = (const float*)d_in[7];
  const float* bG = (const float*)d_in[8];
  const float* dc = (const float*)d_in[9];
  const float* ke = (const float*)d_in[10];
  const float* ki = (const float*)d_in[11];
  float* out = (float*)d_out;

  k_fwd  <<<B_*T_*8,   256>>>(x);
  k_gates<<<B_*T_,     32>>>(wA,bA,wD,bD,wM,bM,wG,bG,dc);
  k_kf   <<<2*C_,      256>>>(ke, ki);
  k_mid  <<<B_*C_*WR_, 256>>>();
  k_inv  <<<B_*T_*C_,  256>>>(out);
}

// round 4
// speedup vs baseline: 2.3916x; 2.2906x over previous
#include <cuda_runtime.h>
#include <math.h>

#define B_ 2
#define T_ 32
#define H_ 64
#define W_ 64
#define C_ 32
#define WR_ 33
#define KS_ 15

// Intermediates (allocation-free: __device__ globals)
__device__ float2 d_R [B_*C_*WR_*T_*H_];   // (B,C,Wr,T,H) row-FFT output (h spatial)
__device__ float2 d_Yr[B_*C_*WR_*T_*H_];   // (B,C,Wr,T,H) after col-inv FFT
__device__ float2 d_Kf[2*C_*WR_*H_];       // (2,C,Wr,slot) kernel spectra, slot-permuted
__device__ float  d_ctx[B_*T_*C_];
__device__ float  d_gates[B_*C_*4*T_];     // (B,C,[a,d,m,g],T)

__device__ __forceinline__ float2 cmul(float2 a, float2 b){
  return make_float2(a.x*b.x - a.y*b.y, a.x*b.y + a.y*b.x);
}

// ---------------- register FFT8, DIF + output reorder to natural order ----------------
template<int INV>
__device__ __forceinline__ void fft8r(float2 v[8]){
  const float S = 0.70710678118654752f;
  {
    float2 u, w, d;
    u=v[0]; w=v[4]; v[0]=make_float2(u.x+w.x,u.y+w.y); v[4]=make_float2(u.x-w.x,u.y-w.y);
    u=v[1]; w=v[5]; v[1]=make_float2(u.x+w.x,u.y+w.y); d=make_float2(u.x-w.x,u.y-w.y);
    v[5]= INV? make_float2(S*(d.x-d.y), S*(d.x+d.y)) : make_float2(S*(d.x+d.y), S*(d.y-d.x));
    u=v[2]; w=v[6]; v[2]=make_float2(u.x+w.x,u.y+w.y); d=make_float2(u.x-w.x,u.y-w.y);
    v[6]= INV? make_float2(-d.y, d.x) : make_float2(d.y, -d.x);
    u=v[3]; w=v[7]; v[3]=make_float2(u.x+w.x,u.y+w.y); d=make_float2(u.x-w.x,u.y-w.y);
    v[7]= INV? make_float2(-S*(d.x+d.y), S*(d.x-d.y)) : make_float2(S*(d.y-d.x), -S*(d.x+d.y));
  }
  #pragma unroll
  for (int h=0; h<8; h+=4){
    float2 u, w, d;
    u=v[h];   w=v[h+2]; v[h]  =make_float2(u.x+w.x,u.y+w.y); v[h+2]=make_float2(u.x-w.x,u.y-w.y);
    u=v[h+1]; w=v[h+3]; v[h+1]=make_float2(u.x+w.x,u.y+w.y); d=make_float2(u.x-w.x,u.y-w.y);
    v[h+3]= INV? make_float2(-d.y, d.x) : make_float2(d.y, -d.x);
  }
  #pragma unroll
  for (int h=0; h<8; h+=2){
    float2 u=v[h], w=v[h+1];
    v[h]  =make_float2(u.x+w.x,u.y+w.y);
    v[h+1]=make_float2(u.x-w.x,u.y-w.y);
  }
  float2 t1=v[1]; v[1]=v[4]; v[4]=t1;
  float2 t3=v[3]; v[3]=v[6]; v[6]=t3;
}

// ---------------- register FFT64 over 8 lanes x 8 regs ----------------
// Forward: input (lane j=n2, reg n1): x[8*n1+j] -> output (lane k1, reg k2): X[k1+8*k2]
template<int INV>
__device__ __forceinline__ void fft64r(float2 v[8], const float2 tw[8], int lane8){
  fft8r<INV>(v);
  #pragma unroll
  for (int r=1;r<8;r++){
    float2 w = tw[r];
    if (INV) w.y = -w.y;
    v[r] = cmul(v[r], w);
  }
  #pragma unroll
  for (int m=4; m; m>>=1){
    #pragma unroll
    for (int i=0;i<8;i++){
      if (i & m) continue;
      bool up = (lane8 & m) != 0;
      float2 send = up ? v[i] : v[i+m];
      float2 got;
      got.x = __shfl_xor_sync(0xffffffffu, send.x, m);
      got.y = __shfl_xor_sync(0xffffffffu, send.y, m);
      if (up) v[i] = got; else v[i+m] = got;
    }
  }
  fft8r<INV>(v);
}

__device__ __forceinline__ void make_tw(float2 tw[8], int j){
  tw[0] = make_float2(1.f, 0.f);
  #pragma unroll
  for (int r=1;r<8;r++){
    float s, c;
    __sincosf(-0.098174770424681f * (float)(j*r), &s, &c);
    tw[r] = make_float2(c, s);
  }
}

// Hermitian partner fetch: rc[r] = Z[(64 - (j+8r)) mod 64], within 8-lane groups.
__device__ __forceinline__ void herm_partner(const float2 v[8], float2 rc[8], int j){
  int src = (8 - j) & 7;
  #pragma unroll
  for (int r=0;r<8;r++){
    float2 send = v[7-r];
    float2 got;
    got.x = __shfl_sync(0xffffffffu, send.x, src, 8);
    got.y = __shfl_sync(0xffffffffu, send.y, src, 8);
    rc[r] = got;
  }
  if (j == 0){
    rc[0]=v[0]; rc[1]=v[7]; rc[2]=v[6]; rc[3]=v[5];
    rc[4]=v[4]; rc[5]=v[3]; rc[6]=v[2]; rc[7]=v[1];
  }
}

// ---------------- K1: row rfft of x (reg FFT) + smem-staged coalesced stores ----------------
// block = (b, t, cg), cg in 0..7 (4 channels each). Stage [4][33][16h pad18] per h-chunk.
__global__ void k_fwd(const float* __restrict__ x){
  __shared__ float2 stg[4*33*18];
  __shared__ float wsum[8][4];
  int tid = threadIdx.x, bid = blockIdx.x;
  int cg = bid & 7, t = (bid>>3) & 31, b = bid >> 8;
  int j = tid & 7, g = tid >> 3;          // 32 groups of 8 lanes
  int p = g & 1, hl = g >> 1;             // parity (channel pair), local h (0..15)
  float2 tw[8]; make_tw(tw, j);
  const float* xb = x + (size_t)(b*T_ + t)*H_*W_*C_;
  int cbase = cg*4 + p*2;
  float a0 = 0.f, a1 = 0.f;

  for (int it=0; it<4; it++){
    int h = it*16 + hl;
    const float* row = xb + (size_t)h*W_*C_ + cbase;
    float2 v[8];
    #pragma unroll
    for (int n1=0;n1<8;n1++){
      float2 z = *(const float2*)(row + (size_t)(8*n1 + j)*C_);
      v[n1] = z; a0 += z.x; a1 += z.y;
    }
    fft64r<0>(v, tw, j);                  // lane=k1, reg=k2, k = j + 8*k2
    float2 rc[8];
    herm_partner(v, rc, j);
    #pragma unroll
    for (int r=0;r<8;r++){
      int k = j + 8*r;
      if (k <= 32){
        float2 A  = make_float2(0.5f*(v[r].x + rc[r].x), 0.5f*(v[r].y - rc[r].y));
        float2 Bv = make_float2(0.5f*(v[r].y + rc[r].y), 0.5f*(rc[r].x - v[r].x));
        stg[((p*2    )*33 + k)*18 + hl] = A;
        stg[((p*2 + 1)*33 + k)*18 + hl] = Bv;
      }
    }
    __syncthreads();
    // cooperative coalesced store: 128B h-runs
    for (int i = tid; i < 4*33*16; i += 256){
      int lc = i / 528;
      int rem = i - lc*528;
      int wr = rem >> 4, hh = rem & 15;
      d_R[((size_t)(b*C_ + cg*4 + lc)*WR_ + wr)*2048 + (size_t)t*64 + it*16 + hh]
        = stg[(lc*33 + wr)*18 + hh];
    }
    __syncthreads();
  }
  // ctx reduction (lane^16 keeps same p; then j bits)
  a0 += __shfl_xor_sync(0xffffffffu, a0, 16);
  a1 += __shfl_xor_sync(0xffffffffu, a1, 16);
  #pragma unroll
  for (int m=4;m;m>>=1){
    a0 += __shfl_xor_sync(0xffffffffu, a0, m);
    a1 += __shfl_xor_sync(0xffffffffu, a1, m);
  }
  int lane = tid & 31, warp = tid >> 5;
  if (lane == 0){ wsum[warp][0]=a0; wsum[warp][1]=a1; }
  if (lane == 8){ wsum[warp][2]=a0; wsum[warp][3]=a1; }
  __syncthreads();
  if (tid < 4){
    float s = 0.f;
    #pragma unroll
    for (int w=0;w<8;w++) s += wsum[w][tid];
    d_ctx[(b*T_ + t)*C_ + cg*4 + tid] = s * (1.0f/4096.0f);
  }
}

// ---------------- K2: gates ----------------
__global__ void k_gates(const float* __restrict__ wA, const float* __restrict__ bA,
                        const float* __restrict__ wD, const float* __restrict__ bD,
                        const float* __restrict__ wM, const float* __restrict__ bM,
                        const float* __restrict__ wG, const float* __restrict__ bG,
                        const float* __restrict__ decay){
  __shared__ float sctx[32];
  int bt = blockIdx.x;
  int c = threadIdx.x;
  sctx[c] = d_ctx[bt*32 + c];
  __syncwarp();
  float za = bA[c], zd = bD[c], zm = bM[c], zg = bG[c];
  #pragma unroll
  for (int k = 0; k < 32; k++){
    float v = sctx[k];
    za += v * wA[k*32 + c];
    zd += v * wD[k*32 + c];
    zm += v * wM[k*32 + c];
    zg += v * wG[k*32 + c];
  }
  float dec = fminf(fmaxf(decay[c], 0.1f), 0.99f);
  float ga = dec / (1.0f + expf(-za));
  float gd = dec / (1.0f + expf(-zd));
  float gm = (zm > 20.0f) ? zm : log1pf(expf(zm));
  float gg = (zg > 20.0f) ? zg : log1pf(expf(zg));
  int b = bt >> 5, t = bt & 31;
  int base = (b*32 + c)*128 + t;
  d_gates[base +  0] = ga;
  d_gates[base + 32] = gd;
  d_gates[base + 64] = gm;
  d_gates[base + 96] = gg;
}

// ---------------- K3: padded rfft2 of conv kernels, slot-permuted column spectra ----------------
__global__ void k_kf(const float* __restrict__ ke, const float* __restrict__ ki){
  __shared__ float2 sb[WR_*64];       // [wr][h spatial]
  int tid = threadIdx.x;
  int e = blockIdx.x >> 5, c = blockIdx.x & 31;
  const float* kk = (e ? ki : ke) + c*KS_*KS_;
  int j = tid & 7, g = tid >> 3;
  float2 tw[8]; make_tw(tw, j);

  {
    int h0 = g << 1;
    float2 v[8];
    #pragma unroll
    for (int n1=0;n1<8;n1++){
      int w = 8*n1 + j;
      float v0 = 0.f, v1 = 0.f;
      if (w >= 24 && w < 39){
        if (h0   >= 24 && h0   < 39) v0 = kk[(h0  -24)*KS_ + (w-24)];
        if (h0+1 >= 24 && h0+1 < 39) v1 = kk[(h0+1-24)*KS_ + (w-24)];
      }
      v[n1] = make_float2(v0, v1);
    }
    fft64r<0>(v, tw, j);
    float2 rc[8];
    herm_partner(v, rc, j);
    #pragma unroll
    for (int r=0;r<8;r++){
      int k = j + 8*r;
      if (k <= 32){
        float2 A  = make_float2(0.5f*(v[r].x + rc[r].x), 0.5f*(v[r].y - rc[r].y));
        float2 Bv = make_float2(0.5f*(v[r].y + rc[r].y), 0.5f*(rc[r].x - v[r].x));
        sb[k*64 + h0    ] = A;
        sb[k*64 + h0 + 1] = Bv;
      }
    }
  }
  __syncthreads();
  size_t kb = ((size_t)(e*C_ + c)*WR_)*64;
  {
    int wr = g;
    float2 v[8];
    #pragma unroll
    for (int n1=0;n1<8;n1++) v[n1] = sb[wr*64 + 8*n1 + j];
    fft64r<0>(v, tw, j);
    #pragma unroll
    for (int r=0;r<8;r++) d_Kf[kb + (size_t)wr*64 + r*8 + j] = v[r];
  }
  if (tid < 32){
    float2 v[8];
    #pragma unroll
    for (int n1=0;n1<8;n1++) v[n1] = sb[32*64 + 8*n1 + j];
    fft64r<0>(v, tw, j);
    if ((tid >> 3) == 0){
      #pragma unroll
      for (int r=0;r<8;r++) d_Kf[kb + (size_t)32*64 + r*8 + j] = v[r];
    }
  }
}

// ---------------- K4: 2 tiles/block: col reg-FFT + recurrence + inverse col reg-FFT ----------------
__global__ void k_mid(){
  __shared__ float sur[2][32*72];
  __shared__ float sui[2][32*72];
  __shared__ float sg[2][128];
  int tid = threadIdx.x;
  int b0 = blockIdx.x * 2;
  int j = tid & 7, t = tid >> 3;
  float2 tw[8]; make_tw(tw, j);

  if (tid < 128) sg[0][tid]       = d_gates[(b0/33)*128 + tid];
  else           sg[1][tid - 128] = d_gates[((b0+1)/33)*128 + (tid - 128)];

  #pragma unroll
  for (int tt=0; tt<2; tt++){
    size_t rbase = (size_t)(b0 + tt) * 2048;
    float2 v[8];
    #pragma unroll
    for (int n1=0;n1<8;n1++) v[n1] = d_R[rbase + t*64 + 8*n1 + j];
    fft64r<0>(v, tw, j);
    #pragma unroll
    for (int r=0;r<8;r++){
      sur[tt][t*72 + r*8 + j] = v[r].x;
      sui[tt][t*72 + r*8 + j] = v[r].y;
    }
  }
  __syncthreads();

  if (tid < 128){
    int tt = tid >> 6, slot = tid & 63;
    int bid = b0 + tt;
    int bc = bid / 33;
    int wr = bid - bc*33;
    int c  = bc & 31;
    float2 KE = d_Kf[((size_t)(      c)*WR_ + wr)*64 + slot];
    float2 KI = d_Kf[((size_t)(C_ +  c)*WR_ + wr)*64 + slot];
    float2 X = make_float2(0.f,0.f), Y = make_float2(0.f,0.f);
    float* pr = sur[tt]; float* pi = sui[tt];
    const float* g = sg[tt];
    #pragma unroll
    for (int t2=0; t2<32; t2++){
      float a  = g[t2], dd = g[32+t2], m = g[64+t2], gg = g[96+t2];
      float2 U = make_float2(pr[t2*72 + slot], pi[t2*72 + slot]);
      float2 KIY = cmul(KI, Y);
      float2 KEX = cmul(KE, X);
      float2 nX = make_float2(a*X.x - m*KIY.x + U.x, a*X.y - m*KIY.y + U.y);
      float2 nY = make_float2(gg*KEX.x + dd*Y.x + 1e-10f, gg*KEX.y + dd*Y.y);
      pr[t2*72 + slot] = nY.x;
      pi[t2*72 + slot] = nY.y;
      X = nX; Y = nY;
    }
  }
  __syncthreads();

  #pragma unroll
  for (int tt=0; tt<2; tt++){
    size_t rbase = (size_t)(b0 + tt) * 2048;
    float2 v[8];
    #pragma unroll
    for (int r=0;r<8;r++){
      v[r].x = sur[tt][t*72 + r*8 + j];
      v[r].y = sui[tt][t*72 + r*8 + j];
    }
    fft64r<1>(v, tw, j);
    #pragma unroll
    for (int n1=0;n1<8;n1++) d_Yr[rbase + t*64 + 8*n1 + j] = v[n1];
  }
}

// ---------------- K5: inverse row rfft; block = (b,t,8-channel group), h-chunked ----------------
__global__ void k_inv(float* __restrict__ out){
  __shared__ float syr[8*33*9];     // [lc][wr][h8 pad9]
  __shared__ float syi[8*33*9];
  __shared__ float so[8*64*9];      // [h8][w64][c8 pad9]
  int tid = threadIdx.x;
  int bid = blockIdx.x;
  int cg = bid & 3;
  int t  = (bid >> 2) & 31;
  int b  = bid >> 7;
  int j = tid & 7, g = tid >> 3;
  int lc_g = g & 7, pr = g >> 3;     // group channel, local h-pair (0..3)
  float2 tw[8]; make_tw(tw, j);
  const float sc = 1.0f/4096.0f;
  size_t obase = ((size_t)(b*T_ + t)*4096)*32 + cg*8;

  for (int hc = 0; hc < 8; hc++){
    // stage A: coalesced load of d_Yr chunk (8c x 33wr x 8h)
    for (int i = tid; i < 8*33*8; i += 256){
      int lc = i >> 8;               // i / 264
      int rem = i - lc*264;
      int wr = rem >> 3, hl = rem & 7;
      float2 z = d_Yr[((size_t)(b*C_ + cg*8 + lc)*WR_ + wr)*2048 + (size_t)t*64 + hc*8 + hl];
      syr[(lc*33 + wr)*9 + hl] = z.x;
      syi[(lc*33 + wr)*9 + hl] = z.y;
    }
    __syncthreads();
    // stage B: Hermitian-extend + reg iFFT for (lc_g, h-pair 2pr/2pr+1)
    {
      float2 v[8];
      #pragma unroll
      for (int r=0;r<8;r++){
        int k = j + 8*r;
        int wrk = (k <= 32) ? k : 64 - k;
        float sgn = (k <= 32) ? 1.f : -1.f;
        int base = (lc_g*33 + wrk)*9;
        float y0r = syr[base + 2*pr];
        float y0i = sgn * syi[base + 2*pr];
        float y1r = syr[base + 2*pr + 1];
        float y1i = sgn * syi[base + 2*pr + 1];
        v[r] = make_float2(y0r - y1i, y0i + y1r);
      }
      fft64r<1>(v, tw, j);
      #pragma unroll
      for (int n1=0;n1<8;n1++){
        int w = 8*n1 + j;
        so[((2*pr    )*64 + w)*9 + lc_g] = v[n1].x * sc;
        so[((2*pr + 1)*64 + w)*9 + lc_g] = v[n1].y * sc;
      }
    }
    __syncthreads();
    // stage C: coalesced store (8-channel 32B runs)
    for (int i = tid; i < 8*64*8; i += 256){
      int lc = i & 7;
      int w  = (i >> 3) & 63;
      int hl = i >> 9;
      out[obase + (size_t)((hc*8 + hl)*64 + w)*32 + lc] = so[(hl*64 + w)*9 + lc];
    }
    __syncthreads();
  }
}

extern "C" void kernel_launch(void* const* d_in, const int* in_sizes, int n_in,
                              void* d_out, int out_size){
  const float* x  = (const float*)d_in[0];
  const float* wA = (const float*)d_in[1];
  const float* bA = (const float*)d_in[2];
  const float* wD = (const float*)d_in[3];
  const float* bD = (const float*)d_in[4];
  const float* wM = (const float*)d_in[5];
  const float* bM = (const float*)d_in[6];
  const float* wG = (const float*)d_in[7];
  const float* bG = (const float*)d_in[8];
  const float* dc = (const float*)d_in[9];
  const float* ke = (const float*)d_in[10];
  const float* ki = (const float*)d_in[11];
  float* out = (float*)d_out;

  k_fwd  <<<B_*T_*8,     256>>>(x);
  k_gates<<<B_*T_,       32>>>(wA,bA,wD,bD,wM,bM,wG,bG,dc);
  k_kf   <<<2*C_,        256>>>(ke, ki);
  k_mid  <<<B_*C_*WR_/2, 256>>>();
  k_inv  <<<B_*T_*4,     256>>>(out);
}

// round 5
// speedup vs baseline: 2.5188x; 1.0532x over previous
#include <cuda_runtime.h>
#include <cuda_fp16.h>
#include <math.h>

#define B_ 2
#define T_ 32
#define H_ 64
#define W_ 64
#define C_ 32
#define WR_ 33
#define KS_ 15

// Intermediates (allocation-free: __device__ globals). fp16 re/im packed.
__device__ __half2 d_R [B_*C_*WR_*T_*H_];  // (B,C,Wr,T,H) row-FFT output (h spatial)
__device__ __half2 d_Yr[B_*C_*WR_*T_*H_];  // (B,C,Wr,T,H) after col-inv FFT
__device__ float2  d_Kf[2*C_*WR_*H_];      // (2,C,Wr,slot) kernel spectra, slot-permuted
__device__ float   d_ctx[B_*T_*C_];
__device__ float   d_gates[B_*C_*4*T_];    // (B,C,[a,d,m,g],T)

__device__ __forceinline__ float2 cmul(float2 a, float2 b){
  return make_float2(a.x*b.x - a.y*b.y, a.x*b.y + a.y*b.x);
}

// ---------------- register FFT8, DIF + output reorder to natural order ----------------
template<int INV>
__device__ __forceinline__ void fft8r(float2 v[8]){
  const float S = 0.70710678118654752f;
  {
    float2 u, w, d;
    u=v[0]; w=v[4]; v[0]=make_float2(u.x+w.x,u.y+w.y); v[4]=make_float2(u.x-w.x,u.y-w.y);
    u=v[1]; w=v[5]; v[1]=make_float2(u.x+w.x,u.y+w.y); d=make_float2(u.x-w.x,u.y-w.y);
    v[5]= INV? make_float2(S*(d.x-d.y), S*(d.x+d.y)) : make_float2(S*(d.x+d.y), S*(d.y-d.x));
    u=v[2]; w=v[6]; v[2]=make_float2(u.x+w.x,u.y+w.y); d=make_float2(u.x-w.x,u.y-w.y);
    v[6]= INV? make_float2(-d.y, d.x) : make_float2(d.y, -d.x);
    u=v[3]; w=v[7]; v[3]=make_float2(u.x+w.x,u.y+w.y); d=make_float2(u.x-w.x,u.y-w.y);
    v[7]= INV? make_float2(-S*(d.x+d.y), S*(d.x-d.y)) : make_float2(S*(d.y-d.x), -S*(d.x+d.y));
  }
  #pragma unroll
  for (int h=0; h<8; h+=4){
    float2 u, w, d;
    u=v[h];   w=v[h+2]; v[h]  =make_float2(u.x+w.x,u.y+w.y); v[h+2]=make_float2(u.x-w.x,u.y-w.y);
    u=v[h+1]; w=v[h+3]; v[h+1]=make_float2(u.x+w.x,u.y+w.y); d=make_float2(u.x-w.x,u.y-w.y);
    v[h+3]= INV? make_float2(-d.y, d.x) : make_float2(d.y, -d.x);
  }
  #pragma unroll
  for (int h=0; h<8; h+=2){
    float2 u=v[h], w=v[h+1];
    v[h]  =make_float2(u.x+w.x,u.y+w.y);
    v[h+1]=make_float2(u.x-w.x,u.y-w.y);
  }
  float2 t1=v[1]; v[1]=v[4]; v[4]=t1;
  float2 t3=v[3]; v[3]=v[6]; v[6]=t3;
}

// ---------------- register FFT64 over 8 lanes x 8 regs ----------------
// Forward: input (lane j=n2, reg n1): x[8*n1+j] -> output (lane k1, reg k2): X[k1+8*k2]
template<int INV>
__device__ __forceinline__ void fft64r(float2 v[8], const float2 tw[8], int lane8){
  fft8r<INV>(v);
  #pragma unroll
  for (int r=1;r<8;r++){
    float2 w = tw[r];
    if (INV) w.y = -w.y;
    v[r] = cmul(v[r], w);
  }
  #pragma unroll
  for (int m=4; m; m>>=1){
    #pragma unroll
    for (int i=0;i<8;i++){
      if (i & m) continue;
      bool up = (lane8 & m) != 0;
      float2 send = up ? v[i] : v[i+m];
      float2 got;
      got.x = __shfl_xor_sync(0xffffffffu, send.x, m);
      got.y = __shfl_xor_sync(0xffffffffu, send.y, m);
      if (up) v[i] = got; else v[i+m] = got;
    }
  }
  fft8r<INV>(v);
}

__device__ __forceinline__ void make_tw(float2 tw[8], int j){
  tw[0] = make_float2(1.f, 0.f);
  #pragma unroll
  for (int r=1;r<8;r++){
    float s, c;
    __sincosf(-0.098174770424681f * (float)(j*r), &s, &c);
    tw[r] = make_float2(c, s);
  }
}

// Hermitian partner fetch: rc[r] = Z[(64 - (j+8r)) mod 64], within 8-lane groups.
__device__ __forceinline__ void herm_partner(const float2 v[8], float2 rc[8], int j){
  int src = (8 - j) & 7;
  #pragma unroll
  for (int r=0;r<8;r++){
    float2 send = v[7-r];
    float2 got;
    got.x = __shfl_sync(0xffffffffu, send.x, src, 8);
    got.y = __shfl_sync(0xffffffffu, send.y, src, 8);
    rc[r] = got;
  }
  if (j == 0){
    rc[0]=v[0]; rc[1]=v[7]; rc[2]=v[6]; rc[3]=v[5];
    rc[4]=v[4]; rc[5]=v[3]; rc[6]=v[2]; rc[7]=v[1];
  }
}

// ---------------- K1: row rfft of x (reg FFT) + smem-staged coalesced stores ----------------
// block = (b, t, cg), cg in 0..7 (4 channels each). Stage [4][33][16h pad18] per h-chunk.
__global__ void k_fwd(const float* __restrict__ x){
  __shared__ float2 stg[4*33*18];
  __shared__ float wsum[8][4];
  int tid = threadIdx.x, bid = blockIdx.x;
  int cg = bid & 7, t = (bid>>3) & 31, b = bid >> 8;
  int j = tid & 7, g = tid >> 3;          // 32 groups of 8 lanes
  int p = g & 1, hl = g >> 1;             // parity (channel pair), local h (0..15)
  float2 tw[8]; make_tw(tw, j);
  const float* xb = x + (size_t)(b*T_ + t)*H_*W_*C_;
  int cbase = cg*4 + p*2;
  float a0 = 0.f, a1 = 0.f;

  for (int it=0; it<4; it++){
    int h = it*16 + hl;
    const float* row = xb + (size_t)h*W_*C_ + cbase;
    float2 v[8];
    #pragma unroll
    for (int n1=0;n1<8;n1++){
      float2 z = *(const float2*)(row + (size_t)(8*n1 + j)*C_);
      v[n1] = z; a0 += z.x; a1 += z.y;
    }
    fft64r<0>(v, tw, j);                  // lane=k1, reg=k2, k = j + 8*k2
    float2 rc[8];
    herm_partner(v, rc, j);
    #pragma unroll
    for (int r=0;r<8;r++){
      int k = j + 8*r;
      if (k <= 32){
        float2 A  = make_float2(0.5f*(v[r].x + rc[r].x), 0.5f*(v[r].y - rc[r].y));
        float2 Bv = make_float2(0.5f*(v[r].y + rc[r].y), 0.5f*(rc[r].x - v[r].x));
        stg[((p*2    )*33 + k)*18 + hl] = A;
        stg[((p*2 + 1)*33 + k)*18 + hl] = Bv;
      }
    }
    __syncthreads();
    // cooperative coalesced store (fp16 pack): 64B h-runs
    for (int i = tid; i < 4*33*16; i += 256){
      int lc = i / 528;
      int rem = i - lc*528;
      int wr = rem >> 4, hh = rem & 15;
      float2 z = stg[(lc*33 + wr)*18 + hh];
      d_R[((size_t)(b*C_ + cg*4 + lc)*WR_ + wr)*2048 + (size_t)t*64 + it*16 + hh]
        = __floats2half2_rn(z.x, z.y);
    }
    __syncthreads();
  }
  // ctx reduction (lane^16 keeps same p; then j bits)
  a0 += __shfl_xor_sync(0xffffffffu, a0, 16);
  a1 += __shfl_xor_sync(0xffffffffu, a1, 16);
  #pragma unroll
  for (int m=4;m;m>>=1){
    a0 += __shfl_xor_sync(0xffffffffu, a0, m);
    a1 += __shfl_xor_sync(0xffffffffu, a1, m);
  }
  int lane = tid & 31, warp = tid >> 5;
  if (lane == 0){ wsum[warp][0]=a0; wsum[warp][1]=a1; }
  if (lane == 8){ wsum[warp][2]=a0; wsum[warp][3]=a1; }
  __syncthreads();
  if (tid < 4){
    float s = 0.f;
    #pragma unroll
    for (int w=0;w<8;w++) s += wsum[w][tid];
    d_ctx[(b*T_ + t)*C_ + cg*4 + tid] = s * (1.0f/4096.0f);
  }
}

// ---------------- K2: gates ----------------
__global__ void k_gates(const float* __restrict__ wA, const float* __restrict__ bA,
                        const float* __restrict__ wD, const float* __restrict__ bD,
                        const float* __restrict__ wM, const float* __restrict__ bM,
                        const float* __restrict__ wG, const float* __restrict__ bG,
                        const float* __restrict__ decay){
  __shared__ float sctx[32];
  int bt = blockIdx.x;
  int c = threadIdx.x;
  sctx[c] = d_ctx[bt*32 + c];
  __syncwarp();
  float za = bA[c], zd = bD[c], zm = bM[c], zg = bG[c];
  #pragma unroll
  for (int k = 0; k < 32; k++){
    float v = sctx[k];
    za += v * wA[k*32 + c];
    zd += v * wD[k*32 + c];
    zm += v * wM[k*32 + c];
    zg += v * wG[k*32 + c];
  }
  float dec = fminf(fmaxf(decay[c], 0.1f), 0.99f);
  float ga = dec / (1.0f + expf(-za));
  float gd = dec / (1.0f + expf(-zd));
  float gm = (zm > 20.0f) ? zm : log1pf(expf(zm));
  float gg = (zg > 20.0f) ? zg : log1pf(expf(zg));
  int b = bt >> 5, t = bt & 31;
  int base = (b*32 + c)*128 + t;
  d_gates[base +  0] = ga;
  d_gates[base + 32] = gd;
  d_gates[base + 64] = gm;
  d_gates[base + 96] = gg;
}

// ---------------- K3: padded rfft2 of conv kernels, slot-permuted column spectra ----------------
__global__ void k_kf(const float* __restrict__ ke, const float* __restrict__ ki){
  __shared__ float2 sb[WR_*64];       // [wr][h spatial]
  int tid = threadIdx.x;
  int e = blockIdx.x >> 5, c = blockIdx.x & 31;
  const float* kk = (e ? ki : ke) + c*KS_*KS_;
  int j = tid & 7, g = tid >> 3;
  float2 tw[8]; make_tw(tw, j);

  {
    int h0 = g << 1;
    float2 v[8];
    #pragma unroll
    for (int n1=0;n1<8;n1++){
      int w = 8*n1 + j;
      float v0 = 0.f, v1 = 0.f;
      if (w >= 24 && w < 39){
        if (h0   >= 24 && h0   < 39) v0 = kk[(h0  -24)*KS_ + (w-24)];
        if (h0+1 >= 24 && h0+1 < 39) v1 = kk[(h0+1-24)*KS_ + (w-24)];
      }
      v[n1] = make_float2(v0, v1);
    }
    fft64r<0>(v, tw, j);
    float2 rc[8];
    herm_partner(v, rc, j);
    #pragma unroll
    for (int r=0;r<8;r++){
      int k = j + 8*r;
      if (k <= 32){
        float2 A  = make_float2(0.5f*(v[r].x + rc[r].x), 0.5f*(v[r].y - rc[r].y));
        float2 Bv = make_float2(0.5f*(v[r].y + rc[r].y), 0.5f*(rc[r].x - v[r].x));
        sb[k*64 + h0    ] = A;
        sb[k*64 + h0 + 1] = Bv;
      }
    }
  }
  __syncthreads();
  size_t kb = ((size_t)(e*C_ + c)*WR_)*64;
  {
    int wr = g;
    float2 v[8];
    #pragma unroll
    for (int n1=0;n1<8;n1++) v[n1] = sb[wr*64 + 8*n1 + j];
    fft64r<0>(v, tw, j);
    #pragma unroll
    for (int r=0;r<8;r++) d_Kf[kb + (size_t)wr*64 + r*8 + j] = v[r];
  }
  if (tid < 32){
    float2 v[8];
    #pragma unroll
    for (int n1=0;n1<8;n1++) v[n1] = sb[32*64 + 8*n1 + j];
    fft64r<0>(v, tw, j);
    if ((tid >> 3) == 0){
      #pragma unroll
      for (int r=0;r<8;r++) d_Kf[kb + (size_t)32*64 + r*8 + j] = v[r];
    }
  }
}

// ---------------- K4: 2 tiles/block: col reg-FFT + recurrence + inverse col reg-FFT ----------------
__global__ void k_mid(){
  __shared__ float sur[2][32*72];
  __shared__ float sui[2][32*72];
  __shared__ float sg[2][128];
  int tid = threadIdx.x;
  int b0 = blockIdx.x * 2;
  int j = tid & 7, t = tid >> 3;
  float2 tw[8]; make_tw(tw, j);

  if (tid < 128) sg[0][tid]       = d_gates[(b0/33)*128 + tid];
  else           sg[1][tid - 128] = d_gates[((b0+1)/33)*128 + (tid - 128)];

  #pragma unroll
  for (int tt=0; tt<2; tt++){
    size_t rbase = (size_t)(b0 + tt) * 2048;
    float2 v[8];
    #pragma unroll
    for (int n1=0;n1<8;n1++) v[n1] = __half22float2(d_R[rbase + t*64 + 8*n1 + j]);
    fft64r<0>(v, tw, j);
    #pragma unroll
    for (int r=0;r<8;r++){
      sur[tt][t*72 + r*8 + j] = v[r].x;
      sui[tt][t*72 + r*8 + j] = v[r].y;
    }
  }
  __syncthreads();

  if (tid < 128){
    int tt = tid >> 6, slot = tid & 63;
    int bid = b0 + tt;
    int bc = bid / 33;
    int wr = bid - bc*33;
    int c  = bc & 31;
    float2 KE = d_Kf[((size_t)(      c)*WR_ + wr)*64 + slot];
    float2 KI = d_Kf[((size_t)(C_ +  c)*WR_ + wr)*64 + slot];
    float2 X = make_float2(0.f,0.f), Y = make_float2(0.f,0.f);
    float* pr = sur[tt]; float* pi = sui[tt];
    const float* g = sg[tt];
    #pragma unroll
    for (int t2=0; t2<32; t2++){
      float a  = g[t2], dd = g[32+t2], m = g[64+t2], gg = g[96+t2];
      float2 U = make_float2(pr[t2*72 + slot], pi[t2*72 + slot]);
      float2 KIY = cmul(KI, Y);
      float2 KEX = cmul(KE, X);
      float2 nX = make_float2(a*X.x - m*KIY.x + U.x, a*X.y - m*KIY.y + U.y);
      float2 nY = make_float2(gg*KEX.x + dd*Y.x + 1e-10f, gg*KEX.y + dd*Y.y);
      pr[t2*72 + slot] = nY.x;
      pi[t2*72 + slot] = nY.y;
      X = nX; Y = nY;
    }
  }
  __syncthreads();

  #pragma unroll
  for (int tt=0; tt<2; tt++){
    size_t rbase = (size_t)(b0 + tt) * 2048;
    float2 v[8];
    #pragma unroll
    for (int r=0;r<8;r++){
      v[r].x = sur[tt][t*72 + r*8 + j];
      v[r].y = sui[tt][t*72 + r*8 + j];
    }
    fft64r<1>(v, tw, j);
    #pragma unroll
    for (int n1=0;n1<8;n1++)
      d_Yr[rbase + t*64 + 8*n1 + j] = __floats2half2_rn(v[n1].x, v[n1].y);
  }
}

// ---------------- K5: inverse row rfft; block = (b,t,8-channel group), h-chunked ----------------
__global__ void k_inv(float* __restrict__ out){
  __shared__ float syr[8*33*9];     // [lc][wr][h8 pad9]
  __shared__ float syi[8*33*9];
  __shared__ float so[8*64*9];      // [h8][w64][c8 pad9]
  int tid = threadIdx.x;
  int bid = blockIdx.x;
  int cg = bid & 3;
  int t  = (bid >> 2) & 31;
  int b  = bid >> 7;
  int j = tid & 7, g = tid >> 3;
  int lc_g = g & 7, pr = g >> 3;     // group channel, local h-pair (0..3)
  float2 tw[8]; make_tw(tw, j);
  const float sc = 1.0f/4096.0f;
  size_t obase = ((size_t)(b*T_ + t)*4096)*32 + cg*8;

  for (int hc = 0; hc < 8; hc++){
    // stage A: coalesced load of d_Yr chunk (8c x 33wr x 8h)
    for (int i = tid; i < 8*33*8; i += 256){
      int lc = i >> 8;               // i / 264
      int rem = i - lc*264;
      int wr = rem >> 3, hl = rem & 7;
      float2 z = __half22float2(
        d_Yr[((size_t)(b*C_ + cg*8 + lc)*WR_ + wr)*2048 + (size_t)t*64 + hc*8 + hl]);
      syr[(lc*33 + wr)*9 + hl] = z.x;
      syi[(lc*33 + wr)*9 + hl] = z.y;
    }
    __syncthreads();
    // stage B: Hermitian-extend + reg iFFT for (lc_g, h-pair 2pr/2pr+1)
    {
      float2 v[8];
      #pragma unroll
      for (int r=0;r<8;r++){
        int k = j + 8*r;
        int wrk = (k <= 32) ? k : 64 - k;
        float sgn = (k <= 32) ? 1.f : -1.f;
        int base = (lc_g*33 + wrk)*9;
        float y0r = syr[base + 2*pr];
        float y0i = sgn * syi[base + 2*pr];
        float y1r = syr[base + 2*pr + 1];
        float y1i = sgn * syi[base + 2*pr + 1];
        v[r] = make_float2(y0r - y1i, y0i + y1r);
      }
      fft64r<1>(v, tw, j);
      #pragma unroll
      for (int n1=0;n1<8;n1++){
        int w = 8*n1 + j;
        so[((2*pr    )*64 + w)*9 + lc_g] = v[n1].x * sc;
        so[((2*pr + 1)*64 + w)*9 + lc_g] = v[n1].y * sc;
      }
    }
    __syncthreads();
    // stage C: coalesced store (8-channel 32B runs)
    for (int i = tid; i < 8*64*8; i += 256){
      int lc = i & 7;
      int w  = (i >> 3) & 63;
      int hl = i >> 9;
      out[obase + (size_t)((hc*8 + hl)*64 + w)*32 + lc] = so[(hl*64 + w)*9 + lc];
    }
    __syncthreads();
  }
}

extern "C" void kernel_launch(void* const* d_in, const int* in_sizes, int n_in,
                              void* d_out, int out_size){
  const float* x  = (const float*)d_in[0];
  const float* wA = (const float*)d_in[1];
  const float* bA = (const float*)d_in[2];
  const float* wD = (const float*)d_in[3];
  const float* bD = (const float*)d_in[4];
  const float* wM = (const float*)d_in[5];
  const float* bM = (const float*)d_in[6];
  const float* wG = (const float*)d_in[7];
  const float* bG = (const float*)d_in[8];
  const float* dc = (const float*)d_in[9];
  const float* ke = (const float*)d_in[10];
  const float* ki = (const float*)d_in[11];
  float* out = (float*)d_out;

  k_fwd  <<<B_*T_*8,     256>>>(x);
  k_gates<<<B_*T_,       32>>>(wA,bA,wD,bD,wM,bM,wG,bG,dc);
  k_kf   <<<2*C_,        256>>>(ke, ki);
  k_mid  <<<B_*C_*WR_/2, 256>>>();
  k_inv  <<<B_*T_*4,     256>>>(out);
}